// round 16
// baseline (speedup 1.0000x reference)
#include <cuda_runtime.h>

typedef unsigned long long u64;
typedef unsigned int u32;

// ---- packed f32x2 helpers ----
__device__ __forceinline__ u64 pk2(float a, float b) {
    u64 r; asm("mov.b64 %0,{%1,%2};" : "=l"(r) : "f"(a), "f"(b)); return r;
}
__device__ __forceinline__ u64 bc2(float a) {
    u64 r; asm("mov.b64 %0,{%1,%1};" : "=l"(r) : "f"(a)); return r;
}
__device__ __forceinline__ void upk2(u64 v, float& a, float& b) {
    asm("mov.b64 {%0,%1},%2;" : "=f"(a), "=f"(b) : "l"(v));
}
__device__ __forceinline__ u64 f2fma(u64 a, u64 b, u64 c) {
    u64 d; asm("fma.rn.f32x2 %0,%1,%2,%3;" : "=l"(d) : "l"(a), "l"(b), "l"(c)); return d;
}
__device__ __forceinline__ u64 f2mul(u64 a, u64 b) {
    u64 d; asm("mul.rn.f32x2 %0,%1,%2;" : "=l"(d) : "l"(a), "l"(b)); return d;
}
__device__ __forceinline__ u64 f2add(u64 a, u64 b) {
    u64 d; asm("add.rn.f32x2 %0,%1,%2;" : "=l"(d) : "l"(a), "l"(b)); return d;
}
__device__ __forceinline__ u64 f2sub(u64 a, u64 b) {   // FADD2: 2 operands
    u64 d; asm("sub.rn.f32x2 %0,%1,%2;" : "=l"(d) : "l"(a), "l"(b)); return d;
}
__device__ __forceinline__ u64 f2neg(u64 a) {          // LOP3 on ALU pipe
    return a ^ 0x8000000080000000ULL;
}
__device__ __forceinline__ float frcp(float a) {
    float r; asm("rcp.approx.f32 %0, %1;" : "=f"(r) : "f"(a)); return r;
}

// CONVERGED kernel (single graph node). Sits at the FFMA2 RF-banking
// roofline (3-distinct-u64-operand rt=3/SMSP): measured issue% matches the
// Σrt model. All levers benchmark-tested across R1-R15; op count is at the
// audited algebraic minimum (tan-form gates, commuted layer-2 RX, RY3 and
// CNOT/measurement folds, distributed Z3, split accumulation chains).
__global__ void __launch_bounds__(128)
qml_main(const float* __restrict__ x, const float* __restrict__ w,
         float* __restrict__ out, int npairs) {
    const unsigned FULL = 0xffffffffu;
    int idx = blockIdx.x * blockDim.x + threadIdx.x;
    int lane = threadIdx.x & 31;
    int cidx = idx < npairs ? idx : npairs - 1;   // keep warp converged for shfl

    const float4* xg = reinterpret_cast<const float4*>(x);
    float4* o4 = reinterpret_cast<float4*>(out);

    float4 xa = xg[2 * cidx];
    float4 xb = xg[2 * cidx + 1];

    // ---- warp-distributed weight trig: lane l handles one angle ----
    //   lanes 0..7  : 0.5*w[l]     (layer-1 ry,rz for q0..q3)
    //   lanes 8..11 : 0.5*w[2l-8]  (layer-2 ry: w[8],w[10],w[12],w[14])
    float s_l, c_l, t_l;
    {
        int wi = lane < 8 ? lane : (lane < 12 ? 2 * lane - 8 : 0);
        __sincosf(0.5f * w[wi], &s_l, &c_l);
        t_l = s_l * frcp(c_l);
    }

    // ---- per-sample trig, software-pipelined per qubit ----
    u64 tx[4];
    u64 vr[4][2], vi[4][2];
    u64 gc;
    {
        float xav[4] = { xa.x, xa.y, xa.z, xa.w };
        float xbv[4] = { xb.x, xb.y, xb.z, xb.w };
        u64 gcp[4];
#pragma unroll
        for (int q = 0; q < 4; q++) {
            float sA, cA, sB, cB;
            __sincosf(0.5f * xav[q], &sA, &cA);
            __sincosf(0.5f * xbv[q], &sB, &cB);
            gcp[q] = pk2(cA, cB);
            u64 s2 = pk2(sA, sB);
            u64 r2 = pk2(frcp(cA), frcp(cB));
            tx[q] = f2mul(s2, r2);

            // layer-1 factor for q (weight trig via shfl)
            float sry = __shfl_sync(FULL, s_l, 2 * q);
            float cry = __shfl_sync(FULL, c_l, 2 * q);
            float srz = __shfl_sync(FULL, s_l, 2 * q + 1);
            float crz = __shfl_sync(FULL, c_l, 2 * q + 1);
            float A = cry * crz, Bv = cry * srz, C = sry * crz, D = sry * srz;
            vr[q][0] = f2fma(tx[q], bc2(D),  bc2(A));
            vi[q][0] = f2fma(tx[q], bc2(C),  bc2(-Bv));
            vr[q][1] = f2fma(tx[q], bc2(Bv), bc2(C));
            vi[q][1] = f2fma(tx[q], bc2(-A), bc2(D));
        }
        gc = f2mul(f2mul(gcp[0], gcp[1]), f2mul(gcp[2], gcp[3]));
    }

    // ---- layer-2 weight scalars via shfl ----
    u64 tw[3];
    float cp2f, A3f, B3f;
    {
        tw[0] = bc2(__shfl_sync(FULL, t_l, 8));
        tw[1] = bc2(__shfl_sync(FULL, t_l, 9));
        tw[2] = bc2(__shfl_sync(FULL, t_l, 10));
        float c8  = __shfl_sync(FULL, c_l, 8);
        float c9  = __shfl_sync(FULL, c_l, 9);
        float c10 = __shfl_sync(FULL, c_l, 10);
        float cp = c8 * c9 * c10;
        cp2f = cp * cp;
        float s11 = __shfl_sync(FULL, s_l, 11);
        float c11 = __shfl_sync(FULL, c_l, 11);
        A3f = c11 * c11 - s11 * s11;    // cos(w3)
        B3f = -4.0f * c11 * s11;        // -2 sin(w3)
    }

    // ==== Layer-2 RX gates commuted backward through layer-1's CNOTs:
    //   RX3 stays; RX2->RXX(2,3); RX1->RXX(1,2); RX0->RXX(0,1). Tan form. ====

    // RX(x3)/c on qubit-3 factor
    u64 wr[2], wi2[2];
    {
        u64 ntx3 = f2neg(tx[3]);
        wr[0]  = f2fma(tx[3], vi[3][1], vr[3][0]);
        wi2[0] = f2fma(ntx3,  vr[3][1], vi[3][0]);
        wr[1]  = f2fma(tx[3], vi[3][0], vr[3][1]);
        wi2[1] = f2fma(ntx3,  vr[3][0], vi[3][1]);
    }

    // Psi23 = v2' (x) w, then RXX(x2)/c (mask 3)
    u64 Qr[4], Qi[4];
    {
        u64 Pr[4], Pi[4];
        u64 nv2i0 = f2neg(vi[2][0]), nv2i1 = f2neg(vi[2][1]);
#pragma unroll
        for (int a = 0; a < 2; a++) {
            u64 ar = vr[2][a], ai = vi[2][a], nai = (a == 0) ? nv2i0 : nv2i1;
#pragma unroll
            for (int b = 0; b < 2; b++) {
                int j = a * 2 + b;
                Pr[j] = f2fma(nai, wi2[b], f2mul(ar, wr[b]));
                Pi[j] = f2fma(ai,  wr[b],  f2mul(ar, wi2[b]));
            }
        }
        u64 ntx2 = f2neg(tx[2]);
#pragma unroll
        for (int k = 0; k < 4; k++) {
            Qr[k] = f2fma(tx[2], Pi[k ^ 3], Pr[k]);
            Qi[k] = f2fma(ntx2,  Pr[k ^ 3], Pi[k]);
        }
    }

    // Phi123 = v1' (x) Q, then RXX(x1)/c (mask 6). Fused pairwise.
    u64 Fr[8], Fi[8];
    {
        u64 nv1i0 = f2neg(vi[1][0]), nv1i1 = f2neg(vi[1][1]);
        u64 ntx1 = f2neg(tx[1]);
#pragma unroll
        for (int j = 0; j < 4; j++) {
            int j2 = j ^ 6;
            int t1 = j & 3, t2 = j2 & 3;   // a1=0, a2=1
            u64 p1r = f2fma(nv1i0,    Qi[t1], f2mul(vr[1][0], Qr[t1]));
            u64 p1i = f2fma(vi[1][0], Qr[t1], f2mul(vr[1][0], Qi[t1]));
            u64 p2r = f2fma(nv1i1,    Qi[t2], f2mul(vr[1][1], Qr[t2]));
            u64 p2i = f2fma(vi[1][1], Qr[t2], f2mul(vr[1][1], Qi[t2]));
            Fr[j]  = f2fma(tx[1], p2i, p1r);
            Fi[j]  = f2fma(ntx1,  p2r, p1i);
            Fr[j2] = f2fma(tx[1], p1i, p2r);
            Fi[j2] = f2fma(ntx1,  p1r, p2i);
        }
    }

    // Full state = v0' (x) F, then RXX(x0)/c (mask 12). Fused pairwise.
    u64 re[16], im[16];
    {
        u64 nv0i0 = f2neg(vi[0][0]), nv0i1 = f2neg(vi[0][1]);
        u64 ntx0 = f2neg(tx[0]);
#pragma unroll
        for (int t = 0; t < 8; t++) {
            int k1 = t;
            int k2 = 8 + (t ^ 4);
            int t2 = t ^ 4;
            u64 p1r = f2fma(nv0i0,    Fi[t],  f2mul(vr[0][0], Fr[t]));
            u64 p1i = f2fma(vi[0][0], Fr[t],  f2mul(vr[0][0], Fi[t]));
            u64 p2r = f2fma(nv0i1,    Fi[t2], f2mul(vr[0][1], Fr[t2]));
            u64 p2i = f2fma(vi[0][1], Fr[t2], f2mul(vr[0][1], Fi[t2]));
            re[k1] = f2fma(tx[0], p2i, p1r);
            im[k1] = f2fma(ntx0,  p2r, p1i);
            re[k2] = f2fma(tx[0], p1i, p2r);
            im[k2] = f2fma(ntx0,  p1r, p2i);
        }
    }

    // ---- layer-1 CNOT chain: basis permutation (register renames) ----
#pragma unroll
    for (int c = 0; c < 3; c++) {
        int bcm = 8 >> c, btm = 8 >> (c + 1);
#pragma unroll
        for (int k = 0; k < 16; k++)
            if ((k & bcm) && !(k & btm)) {
                u64 tr = re[k]; re[k] = re[k | btm]; re[k | btm] = tr;
                u64 ti = im[k]; im[k] = im[k | btm]; im[k | btm] = ti;
            }
    }

    // ---- layer-2 RY qubits 0..2, fast-Givens: n0 = a0 - t a1; n1 = t a0 + a1 ----
#pragma unroll
    for (int q = 0; q < 3; q++) {
        int bq = 8 >> q;
        u64 tq = tw[q];
        u64 ntq = f2neg(tq);
#pragma unroll
        for (int k = 0; k < 16; k++)
            if (!(k & bq)) {
                int k1 = k | bq;
                u64 n0r = f2fma(ntq, re[k1], re[k]);
                u64 n0i = f2fma(ntq, im[k1], im[k]);
                u64 n1r = f2fma(tq, re[k], re[k1]);
                u64 n1i = f2fma(tq, im[k], im[k1]);
                re[k] = n0r; im[k] = n0i; re[k1] = n1r; im[k1] = n1i;
            }
    }

    // ---- per-sample global scale, hoisted to overlap the quadratics ----
    u64 g2t;
    {
        u64 gc2 = f2mul(gc, gc);
        g2t = f2mul(f2mul(gc2, gc2), bc2(cp2f));
    }
    u64 A3g = bc2(A3f), B3g = bc2(B3f);

    // ---- quadratics; Z3 fully distributed; xx via four independent
    //      half-chains (shortened serial FMA tail):
    //   Z3 = g2t * [ A3 * (zp - zm)  +  B3 * ((xxp0+xxp1) - (xxm0+xxm1)) ]
    //   + for parity-even j {0,3,5,6}, − for {1,2,4,7}.
    u64 s01[8];
    u64 zp, zm;
    u64 xxp0, xxp1, xxm0, xxm1;
#pragma unroll
    for (int j = 0; j < 8; j++) {
        int k0 = 2 * j, k1 = 2 * j + 1;
        u64 q0 = f2fma(im[k0], im[k0], f2mul(re[k0], re[k0]));
        u64 q1 = f2fma(im[k1], im[k1], f2mul(re[k1], re[k1]));
        s01[j] = f2add(q0, q1);
        u64 zj = f2sub(q0, q1);
        if (j == 0) {
            zp   = zj;
            xxp0 = f2fma(im[k0], im[k1], f2mul(re[k0], re[k1]));
        } else if (j == 3) {
            zp   = f2add(zp, zj);
            xxp1 = f2fma(im[k0], im[k1], f2mul(re[k0], re[k1]));
        } else if (j == 5) {
            zp   = f2add(zp, zj);
            xxp0 = f2fma(re[k0], re[k1], xxp0);
            xxp0 = f2fma(im[k0], im[k1], xxp0);
        } else if (j == 6) {
            zp   = f2add(zp, zj);
            xxp1 = f2fma(re[k0], re[k1], xxp1);
            xxp1 = f2fma(im[k0], im[k1], xxp1);
        } else if (j == 1) {
            zm   = zj;
            xxm0 = f2fma(im[k0], im[k1], f2mul(re[k0], re[k1]));
        } else if (j == 2) {
            zm   = f2add(zm, zj);
            xxm1 = f2fma(im[k0], im[k1], f2mul(re[k0], re[k1]));
        } else if (j == 4) {
            zm   = f2add(zm, zj);
            xxm0 = f2fma(re[k0], re[k1], xxm0);
            xxm0 = f2fma(im[k0], im[k1], xxm0);
        } else { // j == 7
            zm   = f2add(zm, zj);
            xxm1 = f2fma(re[k0], re[k1], xxm1);
            xxm1 = f2fma(im[k0], im[k1], xxm1);
        }
    }
    u64 zsum  = f2sub(zp, zm);
    u64 xxsum = f2sub(f2add(xxp0, xxp1), f2add(xxm0, xxm1));
    u64 Z3 = f2mul(g2t, f2fma(B3g, xxsum, f2mul(A3g, zsum)));

    // ---- layer-2 CNOTs folded into measurement parities (Walsh) ----
    u64 sq[4], dq[4];
#pragma unroll
    for (int m = 0; m < 4; m++) {
        sq[m] = f2add(s01[2 * m], s01[2 * m + 1]);
        dq[m] = f2sub(s01[2 * m], s01[2 * m + 1]);
    }
    u64 Z2 = f2mul(g2t, f2sub(f2add(dq[0], dq[3]), f2add(dq[1], dq[2])));
    u64 Z1 = f2mul(g2t, f2sub(f2add(sq[0], sq[3]), f2add(sq[1], sq[2])));
    u64 Z0 = f2mul(g2t, f2sub(f2add(sq[0], sq[1]), f2add(sq[2], sq[3])));

    // ---- unpack lanes and store (guarded; loads were clamp-indexed) ----
    if (idx < npairs) {
        float z0a, z0b, z1a, z1b, z2a, z2b, z3a, z3b;
        upk2(Z0, z0a, z0b); upk2(Z1, z1a, z1b);
        upk2(Z2, z2a, z2b); upk2(Z3, z3a, z3b);
        o4[2 * idx]     = make_float4(z0a, z1a, z2a, z3a);
        o4[2 * idx + 1] = make_float4(z0b, z1b, z2b, z3b);
    }
}

extern "C" void kernel_launch(void* const* d_in, const int* in_sizes, int n_in,
                              void* d_out, int out_size) {
    const float* x = (const float*)d_in[0];       // [B,4] float32
    const float* w = (const float*)d_in[1];       // [2,4,2] float32
    float* out = (float*)d_out;                   // [B,4] float32
    int B = in_sizes[0] / 4;
    int npairs = B >> 1;                          // B = 2^20, even

    int block = 128;                              // 5 blocks/SM @94 regs — best geometry
    int grid = (npairs + block - 1) / block;
    qml_main<<<grid, block>>>(x, w, out, npairs);
}

// round 17
// speedup vs baseline: 1.0122x; 1.0122x over previous
#include <cuda_runtime.h>

typedef unsigned long long u64;
typedef unsigned int u32;

// ---- packed f32x2 helpers ----
__device__ __forceinline__ u64 pk2(float a, float b) {
    u64 r; asm("mov.b64 %0,{%1,%2};" : "=l"(r) : "f"(a), "f"(b)); return r;
}
__device__ __forceinline__ u64 bc2(float a) {
    u64 r; asm("mov.b64 %0,{%1,%1};" : "=l"(r) : "f"(a)); return r;
}
__device__ __forceinline__ void upk2(u64 v, float& a, float& b) {
    asm("mov.b64 {%0,%1},%2;" : "=f"(a), "=f"(b) : "l"(v));
}
__device__ __forceinline__ u64 f2fma(u64 a, u64 b, u64 c) {
    u64 d; asm("fma.rn.f32x2 %0,%1,%2,%3;" : "=l"(d) : "l"(a), "l"(b), "l"(c)); return d;
}
__device__ __forceinline__ u64 f2mul(u64 a, u64 b) {
    u64 d; asm("mul.rn.f32x2 %0,%1,%2;" : "=l"(d) : "l"(a), "l"(b)); return d;
}
__device__ __forceinline__ u64 f2add(u64 a, u64 b) {
    u64 d; asm("add.rn.f32x2 %0,%1,%2;" : "=l"(d) : "l"(a), "l"(b)); return d;
}
__device__ __forceinline__ u64 f2sub(u64 a, u64 b) {   // FADD2: 2 operands
    u64 d; asm("sub.rn.f32x2 %0,%1,%2;" : "=l"(d) : "l"(a), "l"(b)); return d;
}
__device__ __forceinline__ u64 f2neg(u64 a) {          // LOP3 on ALU pipe
    return a ^ 0x8000000080000000ULL;
}
__device__ __forceinline__ float frcp(float a) {
    float r; asm("rcp.approx.f32 %0, %1;" : "=f"(r) : "f"(a)); return r;
}

// CONVERGED kernel (single graph node). Sits at the FFMA2 RF-banking
// roofline (3-distinct-u64-operand rt=3/SMSP): measured issue% matches the
// Σrt model across R11-R16. Op count is at the audited algebraic minimum:
// tan-form (fast-Givens) gates with cos factors folded into one global
// probability scale; layer-2 RX commuted backward through layer-1's CNOTs
// (RXX on the partially-expanded product state); layer-1 CNOTs as register
// renames; layer-2 RZ dropped (phase-invisible); RY3 + final CNOTs folded
// into Walsh-parity quadratics with distributed Z3 and split accumulation
// chains. Weight trig warp-distributed via shfl (one __sincosf per lane).
__global__ void __launch_bounds__(128)
qml_main(const float* __restrict__ x, const float* __restrict__ w,
         float* __restrict__ out, int npairs) {
    const unsigned FULL = 0xffffffffu;
    int idx = blockIdx.x * blockDim.x + threadIdx.x;
    int lane = threadIdx.x & 31;
    int cidx = idx < npairs ? idx : npairs - 1;   // keep warp converged for shfl

    const float4* xg = reinterpret_cast<const float4*>(x);
    float4* o4 = reinterpret_cast<float4*>(out);

    float4 xa = xg[2 * cidx];
    float4 xb = xg[2 * cidx + 1];

    // ---- warp-distributed weight trig: lane l handles one angle ----
    //   lanes 0..7  : 0.5*w[l]     (layer-1 ry,rz for q0..q3)
    //   lanes 8..11 : 0.5*w[2l-8]  (layer-2 ry: w[8],w[10],w[12],w[14])
    float s_l, c_l, t_l;
    {
        int wi = lane < 8 ? lane : (lane < 12 ? 2 * lane - 8 : 0);
        __sincosf(0.5f * w[wi], &s_l, &c_l);
        t_l = s_l * frcp(c_l);
    }

    // ---- per-sample trig, software-pipelined per qubit ----
    u64 tx[4];
    u64 vr[4][2], vi[4][2];
    u64 gc;
    {
        float xav[4] = { xa.x, xa.y, xa.z, xa.w };
        float xbv[4] = { xb.x, xb.y, xb.z, xb.w };
        u64 gcp[4];
#pragma unroll
        for (int q = 0; q < 4; q++) {
            float sA, cA, sB, cB;
            __sincosf(0.5f * xav[q], &sA, &cA);
            __sincosf(0.5f * xbv[q], &sB, &cB);
            gcp[q] = pk2(cA, cB);
            u64 s2 = pk2(sA, sB);
            u64 r2 = pk2(frcp(cA), frcp(cB));
            tx[q] = f2mul(s2, r2);

            // layer-1 factor for q (weight trig via shfl)
            float sry = __shfl_sync(FULL, s_l, 2 * q);
            float cry = __shfl_sync(FULL, c_l, 2 * q);
            float srz = __shfl_sync(FULL, s_l, 2 * q + 1);
            float crz = __shfl_sync(FULL, c_l, 2 * q + 1);
            float A = cry * crz, Bv = cry * srz, C = sry * crz, D = sry * srz;
            vr[q][0] = f2fma(tx[q], bc2(D),  bc2(A));
            vi[q][0] = f2fma(tx[q], bc2(C),  bc2(-Bv));
            vr[q][1] = f2fma(tx[q], bc2(Bv), bc2(C));
            vi[q][1] = f2fma(tx[q], bc2(-A), bc2(D));
        }
        gc = f2mul(f2mul(gcp[0], gcp[1]), f2mul(gcp[2], gcp[3]));
    }

    // ---- layer-2 weight scalars via shfl ----
    u64 tw[3];
    float cp2f, A3f, B3f;
    {
        tw[0] = bc2(__shfl_sync(FULL, t_l, 8));
        tw[1] = bc2(__shfl_sync(FULL, t_l, 9));
        tw[2] = bc2(__shfl_sync(FULL, t_l, 10));
        float c8  = __shfl_sync(FULL, c_l, 8);
        float c9  = __shfl_sync(FULL, c_l, 9);
        float c10 = __shfl_sync(FULL, c_l, 10);
        float cp = c8 * c9 * c10;
        cp2f = cp * cp;
        float s11 = __shfl_sync(FULL, s_l, 11);
        float c11 = __shfl_sync(FULL, c_l, 11);
        A3f = c11 * c11 - s11 * s11;    // cos(w3)
        B3f = -4.0f * c11 * s11;        // -2 sin(w3)
    }

    // ==== Layer-2 RX gates commuted backward through layer-1's CNOTs:
    //   RX3 stays; RX2->RXX(2,3); RX1->RXX(1,2); RX0->RXX(0,1). Tan form. ====

    // RX(x3)/c on qubit-3 factor
    u64 wr[2], wi2[2];
    {
        u64 ntx3 = f2neg(tx[3]);
        wr[0]  = f2fma(tx[3], vi[3][1], vr[3][0]);
        wi2[0] = f2fma(ntx3,  vr[3][1], vi[3][0]);
        wr[1]  = f2fma(tx[3], vi[3][0], vr[3][1]);
        wi2[1] = f2fma(ntx3,  vr[3][0], vi[3][1]);
    }

    // Psi23 = v2' (x) w, then RXX(x2)/c (mask 3)
    u64 Qr[4], Qi[4];
    {
        u64 Pr[4], Pi[4];
        u64 nv2i0 = f2neg(vi[2][0]), nv2i1 = f2neg(vi[2][1]);
#pragma unroll
        for (int a = 0; a < 2; a++) {
            u64 ar = vr[2][a], ai = vi[2][a], nai = (a == 0) ? nv2i0 : nv2i1;
#pragma unroll
            for (int b = 0; b < 2; b++) {
                int j = a * 2 + b;
                Pr[j] = f2fma(nai, wi2[b], f2mul(ar, wr[b]));
                Pi[j] = f2fma(ai,  wr[b],  f2mul(ar, wi2[b]));
            }
        }
        u64 ntx2 = f2neg(tx[2]);
#pragma unroll
        for (int k = 0; k < 4; k++) {
            Qr[k] = f2fma(tx[2], Pi[k ^ 3], Pr[k]);
            Qi[k] = f2fma(ntx2,  Pr[k ^ 3], Pi[k]);
        }
    }

    // Phi123 = v1' (x) Q, then RXX(x1)/c (mask 6). Fused pairwise.
    u64 Fr[8], Fi[8];
    {
        u64 nv1i0 = f2neg(vi[1][0]), nv1i1 = f2neg(vi[1][1]);
        u64 ntx1 = f2neg(tx[1]);
#pragma unroll
        for (int j = 0; j < 4; j++) {
            int j2 = j ^ 6;
            int t1 = j & 3, t2 = j2 & 3;   // a1=0, a2=1
            u64 p1r = f2fma(nv1i0,    Qi[t1], f2mul(vr[1][0], Qr[t1]));
            u64 p1i = f2fma(vi[1][0], Qr[t1], f2mul(vr[1][0], Qi[t1]));
            u64 p2r = f2fma(nv1i1,    Qi[t2], f2mul(vr[1][1], Qr[t2]));
            u64 p2i = f2fma(vi[1][1], Qr[t2], f2mul(vr[1][1], Qi[t2]));
            Fr[j]  = f2fma(tx[1], p2i, p1r);
            Fi[j]  = f2fma(ntx1,  p2r, p1i);
            Fr[j2] = f2fma(tx[1], p1i, p2r);
            Fi[j2] = f2fma(ntx1,  p1r, p2i);
        }
    }

    // Full state = v0' (x) F, then RXX(x0)/c (mask 12). Fused pairwise.
    u64 re[16], im[16];
    {
        u64 nv0i0 = f2neg(vi[0][0]), nv0i1 = f2neg(vi[0][1]);
        u64 ntx0 = f2neg(tx[0]);
#pragma unroll
        for (int t = 0; t < 8; t++) {
            int k1 = t;
            int k2 = 8 + (t ^ 4);
            int t2 = t ^ 4;
            u64 p1r = f2fma(nv0i0,    Fi[t],  f2mul(vr[0][0], Fr[t]));
            u64 p1i = f2fma(vi[0][0], Fr[t],  f2mul(vr[0][0], Fi[t]));
            u64 p2r = f2fma(nv0i1,    Fi[t2], f2mul(vr[0][1], Fr[t2]));
            u64 p2i = f2fma(vi[0][1], Fr[t2], f2mul(vr[0][1], Fi[t2]));
            re[k1] = f2fma(tx[0], p2i, p1r);
            im[k1] = f2fma(ntx0,  p2r, p1i);
            re[k2] = f2fma(tx[0], p1i, p2r);
            im[k2] = f2fma(ntx0,  p1r, p2i);
        }
    }

    // ---- layer-1 CNOT chain: basis permutation (register renames) ----
#pragma unroll
    for (int c = 0; c < 3; c++) {
        int bcm = 8 >> c, btm = 8 >> (c + 1);
#pragma unroll
        for (int k = 0; k < 16; k++)
            if ((k & bcm) && !(k & btm)) {
                u64 tr = re[k]; re[k] = re[k | btm]; re[k | btm] = tr;
                u64 ti = im[k]; im[k] = im[k | btm]; im[k | btm] = ti;
            }
    }

    // ---- layer-2 RY qubits 0..2, fast-Givens: n0 = a0 - t a1; n1 = t a0 + a1 ----
#pragma unroll
    for (int q = 0; q < 3; q++) {
        int bq = 8 >> q;
        u64 tq = tw[q];
        u64 ntq = f2neg(tq);
#pragma unroll
        for (int k = 0; k < 16; k++)
            if (!(k & bq)) {
                int k1 = k | bq;
                u64 n0r = f2fma(ntq, re[k1], re[k]);
                u64 n0i = f2fma(ntq, im[k1], im[k]);
                u64 n1r = f2fma(tq, re[k], re[k1]);
                u64 n1i = f2fma(tq, im[k], im[k1]);
                re[k] = n0r; im[k] = n0i; re[k1] = n1r; im[k1] = n1i;
            }
    }

    // ---- per-sample global scale, hoisted to overlap the quadratics ----
    u64 g2t;
    {
        u64 gc2 = f2mul(gc, gc);
        g2t = f2mul(f2mul(gc2, gc2), bc2(cp2f));
    }
    u64 A3g = bc2(A3f), B3g = bc2(B3f);

    // ---- quadratics; Z3 fully distributed; xx via four independent
    //      half-chains (shortened serial FMA tail):
    //   Z3 = g2t * [ A3 * (zp - zm)  +  B3 * ((xxp0+xxp1) - (xxm0+xxm1)) ]
    //   + for parity-even j {0,3,5,6}, − for {1,2,4,7}.
    u64 s01[8];
    u64 zp, zm;
    u64 xxp0, xxp1, xxm0, xxm1;
#pragma unroll
    for (int j = 0; j < 8; j++) {
        int k0 = 2 * j, k1 = 2 * j + 1;
        u64 q0 = f2fma(im[k0], im[k0], f2mul(re[k0], re[k0]));
        u64 q1 = f2fma(im[k1], im[k1], f2mul(re[k1], re[k1]));
        s01[j] = f2add(q0, q1);
        u64 zj = f2sub(q0, q1);
        if (j == 0) {
            zp   = zj;
            xxp0 = f2fma(im[k0], im[k1], f2mul(re[k0], re[k1]));
        } else if (j == 3) {
            zp   = f2add(zp, zj);
            xxp1 = f2fma(im[k0], im[k1], f2mul(re[k0], re[k1]));
        } else if (j == 5) {
            zp   = f2add(zp, zj);
            xxp0 = f2fma(re[k0], re[k1], xxp0);
            xxp0 = f2fma(im[k0], im[k1], xxp0);
        } else if (j == 6) {
            zp   = f2add(zp, zj);
            xxp1 = f2fma(re[k0], re[k1], xxp1);
            xxp1 = f2fma(im[k0], im[k1], xxp1);
        } else if (j == 1) {
            zm   = zj;
            xxm0 = f2fma(im[k0], im[k1], f2mul(re[k0], re[k1]));
        } else if (j == 2) {
            zm   = f2add(zm, zj);
            xxm1 = f2fma(im[k0], im[k1], f2mul(re[k0], re[k1]));
        } else if (j == 4) {
            zm   = f2add(zm, zj);
            xxm0 = f2fma(re[k0], re[k1], xxm0);
            xxm0 = f2fma(im[k0], im[k1], xxm0);
        } else { // j == 7
            zm   = f2add(zm, zj);
            xxm1 = f2fma(re[k0], re[k1], xxm1);
            xxm1 = f2fma(im[k0], im[k1], xxm1);
        }
    }
    u64 zsum  = f2sub(zp, zm);
    u64 xxsum = f2sub(f2add(xxp0, xxp1), f2add(xxm0, xxm1));
    u64 Z3 = f2mul(g2t, f2fma(B3g, xxsum, f2mul(A3g, zsum)));

    // ---- layer-2 CNOTs folded into measurement parities (Walsh) ----
    u64 sq[4], dq[4];
#pragma unroll
    for (int m = 0; m < 4; m++) {
        sq[m] = f2add(s01[2 * m], s01[2 * m + 1]);
        dq[m] = f2sub(s01[2 * m], s01[2 * m + 1]);
    }
    u64 Z2 = f2mul(g2t, f2sub(f2add(dq[0], dq[3]), f2add(dq[1], dq[2])));
    u64 Z1 = f2mul(g2t, f2sub(f2add(sq[0], sq[3]), f2add(sq[1], sq[2])));
    u64 Z0 = f2mul(g2t, f2sub(f2add(sq[0], sq[1]), f2add(sq[2], sq[3])));

    // ---- unpack lanes and store (guarded; loads were clamp-indexed) ----
    if (idx < npairs) {
        float z0a, z0b, z1a, z1b, z2a, z2b, z3a, z3b;
        upk2(Z0, z0a, z0b); upk2(Z1, z1a, z1b);
        upk2(Z2, z2a, z2b); upk2(Z3, z3a, z3b);
        o4[2 * idx]     = make_float4(z0a, z1a, z2a, z3a);
        o4[2 * idx + 1] = make_float4(z0b, z1b, z2b, z3b);
    }
}

extern "C" void kernel_launch(void* const* d_in, const int* in_sizes, int n_in,
                              void* d_out, int out_size) {
    const float* x = (const float*)d_in[0];       // [B,4] float32
    const float* w = (const float*)d_in[1];       // [2,4,2] float32
    float* out = (float*)d_out;                   // [B,4] float32
    int B = in_sizes[0] / 4;
    int npairs = B >> 1;                          // B = 2^20, even

    int block = 128;                              // 5 blocks/SM @94 regs — best geometry
    int grid = (npairs + block - 1) / block;
    qml_main<<<grid, block>>>(x, w, out, npairs);
}